// round 7
// baseline (speedup 1.0000x reference)
#include <cuda_runtime.h>
#include <cuda_bf16.h>
#include <cstdint>

// ---------------- problem constants ----------------
#define HW       16384           // 128*128 pixels per image
#define N_KCHUNK 16              // K = 512 in chunks of 32
#define NTILES   8192            // 1024 m-tiles x 8 n-tiles
#define GRID_MAIN 296            // 148 SMs x 2 CTAs

// ---------------- smem layout ----------------
// stage = A_hi(8K) A_lo(8K) B_hi(8K) B_lo(8K) = 32KB, 3 stages + cent(4KB)
#define STAGE     32768
#define B_REGION  16384
#define CENT_OFF  (3 * STAGE)
#define SMEM_BYTES (CENT_OFF + 4096)

// scratch: features pre-split to bf16 hi/lo in ldmatrix-canonical tiles.
// chunk (mt, kc) = 16KB: hi[8K] lo[8K]; 1024 mt * 16 kc = 256MB
__device__ uint4 g_feat[16777216];
// weights likewise: chunk (bx, kc) = 16KB; 8 * 16 = 2MB
__device__ uint4 g_w[131072];

// ---------------- helpers ----------------
__device__ __forceinline__ uint32_t smem_u32(const void* p) {
    uint32_t a;
    asm("{ .reg .u64 t; cvta.to.shared.u64 t, %1; cvt.u32.u64 %0, t; }" : "=r"(a) : "l"(p));
    return a;
}
#define CP_ASYNC16(dst, src) \
    asm volatile("cp.async.cg.shared.global [%0], [%1], 16;" :: "r"(dst), "l"(src) : "memory")
#define CP_COMMIT()  asm volatile("cp.async.commit_group;" ::: "memory")
#define CP_WAIT1()   asm volatile("cp.async.wait_group 1;" ::: "memory")

__device__ __forceinline__ void ldsm4(uint32_t* r, uint32_t addr) {
    asm volatile("ldmatrix.sync.aligned.m8n8.x4.shared.b16 {%0,%1,%2,%3}, [%4];"
        : "=r"(r[0]), "=r"(r[1]), "=r"(r[2]), "=r"(r[3]) : "r"(addr));
}
__device__ __forceinline__ void mma16816(float* d, const uint32_t* a, const uint32_t* b) {
    asm volatile("mma.sync.aligned.m16n8k16.row.col.f32.bf16.bf16.f32 "
        "{%0,%1,%2,%3}, {%4,%5,%6,%7}, {%8,%9}, {%0,%1,%2,%3};"
        : "+f"(d[0]), "+f"(d[1]), "+f"(d[2]), "+f"(d[3])
        : "r"(a[0]), "r"(a[1]), "r"(a[2]), "r"(a[3]), "r"(b[0]), "r"(b[1]));
}
__device__ __forceinline__ void split2(float x0, float x1, uint32_t& hi, uint32_t& lo) {
    __nv_bfloat16 h0 = __float2bfloat16(x0);
    __nv_bfloat16 h1 = __float2bfloat16(x1);
    __nv_bfloat16 l0 = __float2bfloat16(x0 - __bfloat162float(h0));
    __nv_bfloat16 l1 = __float2bfloat16(x1 - __bfloat162float(h1));
    hi = (uint32_t)__bfloat16_as_ushort(h0) | ((uint32_t)__bfloat16_as_ushort(h1) << 16);
    lo = (uint32_t)__bfloat16_as_ushort(l0) | ((uint32_t)__bfloat16_as_ushort(l1) << 16);
}

// ---------------- prep: features (+weights) -> hi/lo bf16 canonical tiles ----
// blocks 0..16383: features; blocks 16384..16639: weights (n = c*16+e order)
__global__ void prep_all(const float* __restrict__ feat, const float* __restrict__ w) {
    int tid = threadIdx.x;
    if (blockIdx.x >= 16384) {
        int idx = (blockIdx.x - 16384) * 256 + tid;   // n(1024) x k8(64)
        int n = idx >> 6, k8 = idx & 63;
        int e = n & 15, c = n >> 4;
        const float* src = w + (((size_t)(e * 64 + c)) << 9) + k8 * 8;
        uint32_t hiw[4], low[4];
        #pragma unroll
        for (int i = 0; i < 4; i++) split2(src[2 * i], src[2 * i + 1], hiw[i], low[i]);
        int bx = n >> 7, nl = n & 127, kc = k8 >> 2, k8l = k8 & 3;
        char* dst = (char*)g_w + ((size_t)(bx * 16 + kc)) * 16384;
        uint32_t off = (uint32_t)(((nl >> 3) * 4 + k8l) * 128 + (nl & 7) * 16);
        *(uint4*)(dst + off)        = make_uint4(hiw[0], hiw[1], hiw[2], hiw[3]);
        *(uint4*)(dst + 8192 + off) = make_uint4(low[0], low[1], low[2], low[3]);
        return;
    }
    __shared__ float s[32][128];
    int blk = blockIdx.x;                 // mt*16 + kc
    int mt = blk >> 4, kc = blk & 15;
    int b = mt >> 7, ptile = (mt & 127) << 7;
    const float* src = feat + (((size_t)b << 9) + kc * 32) * HW + ptile;
    int px = tid & 127, kh = tid >> 7;    // kh 0..1
    #pragma unroll
    for (int r = 0; r < 16; r++) {
        int k = r * 2 + kh;
        s[k][px] = src[(size_t)k * HW + px];
    }
    __syncthreads();
    char* dst = (char*)g_feat + (size_t)blk * 16384;
    #pragma unroll
    for (int j = 0; j < 2; j++) {
        int k8 = kh * 2 + j;
        uint32_t hiw[4], low[4];
        #pragma unroll
        for (int i = 0; i < 4; i++)
            split2(s[k8 * 8 + 2 * i][px], s[k8 * 8 + 2 * i + 1][px], hiw[i], low[i]);
        uint32_t off = (uint32_t)(((px >> 3) * 4 + k8) * 128 + (px & 7) * 16);
        *(uint4*)(dst + off)        = make_uint4(hiw[0], hiw[1], hiw[2], hiw[3]);
        *(uint4*)(dst + 8192 + off) = make_uint4(low[0], low[1], low[2], low[3]);
    }
}

// ---------------- main fused kernel: persistent, continuous pipeline ----------
__global__ void __launch_bounds__(256, 2)
duq_main(const float* __restrict__ d_m, const float* __restrict__ d_N,
         float* __restrict__ out) {
    extern __shared__ char smem[];
    const uint32_t sb = smem_u32(smem);

    const int tid  = threadIdx.x;
    const int lane = tid & 31;
    const int wid  = tid >> 5;
    const int wr   = wid >> 1;        // warp m-row 0..3  (m offset wr*32)
    const int wc   = wid & 1;         // warp n-col 0..1  (n offset wc*64)

    // all 1024 centroids once: cent[i], i = c*16 + e
    float* centS = (float*)(smem + CENT_OFF);
    if (tid < 256) {
        #pragma unroll
        for (int r = 0; r < 4; r++) {
            int i = r * 256 + tid;
            centS[i] = d_m[(i & 15) * 64 + (i >> 4)] / d_N[i >> 4];
        }
    }

    // chunk loader: tile t = mt*8 + bx; pure cp.async, 8 x 16B per thread
    const uint32_t dstT = sb + tid * 16;
    auto load_chunk = [&](int t, int kc, uint32_t stByte) {
        int mt = t >> 3, bx = t & 7;
        const char* sa = (const char*)(g_feat + (((size_t)(mt * 16 + kc)) << 10)) + tid * 16;
        const char* sp = (const char*)(g_w    + (((size_t)(bx * 16 + kc)) << 10)) + tid * 16;
        #pragma unroll
        for (int it = 0; it < 4; it++)
            CP_ASYNC16(dstT + stByte + it * 4096, sa + it * 4096);
        #pragma unroll
        for (int it = 0; it < 4; it++)
            CP_ASYNC16(dstT + stByte + B_REGION + it * 4096, sp + it * 4096);
    };

    // ldmatrix lane bases (canonical tiled layout, conflict-free)
    const int g = lane >> 3, r8 = lane & 7;
    const uint32_t baseA = sb + (uint32_t)((((wr * 4 + (g & 1)) * 4 + (g >> 1)) * 128) + r8 * 16);
    const uint32_t baseB = sb + (uint32_t)(B_REGION + (((wc * 8 + (g >> 1)) * 4 + (g & 1)) * 128) + r8 * 16);

    float acc[2][8][4];
    #pragma unroll
    for (int i = 0; i < 2; i++)
        #pragma unroll
        for (int j = 0; j < 8; j++)
            #pragma unroll
            for (int k = 0; k < 4; k++) acc[i][j][k] = 0.f;

    // one 16-K step: 12 ldsm.x4, 48 mma, B-frag registers reused hi->lo
    auto compute = [&](int ks, uint32_t st) {
        uint32_t ah[2][4], al[2][4], bb[8][2];
        const uint32_t aoff = baseA + st + ks * 256;
        const uint32_t boff = baseB + st + ks * 256;
        ldsm4(ah[0], aoff);
        ldsm4(ah[1], aoff + 1024);
        ldsm4(al[0], aoff + 8192);
        ldsm4(al[1], aoff + 8192 + 1024);
        #pragma unroll
        for (int t = 0; t < 4; t++) ldsm4(&bb[2 * t][0], boff + t * 1024);
        #pragma unroll
        for (int mi = 0; mi < 2; mi++)
            #pragma unroll
            for (int nj = 0; nj < 8; nj++) mma16816(acc[mi][nj], ah[mi], bb[nj]);  // hi*hi
        #pragma unroll
        for (int mi = 0; mi < 2; mi++)
            #pragma unroll
            for (int nj = 0; nj < 8; nj++) mma16816(acc[mi][nj], al[mi], bb[nj]);  // lo*hi
        #pragma unroll
        for (int t = 0; t < 4; t++) ldsm4(&bb[2 * t][0], boff + 8192 + t * 1024);  // reuse regs
        #pragma unroll
        for (int mi = 0; mi < 2; mi++)
            #pragma unroll
            for (int nj = 0; nj < 8; nj++) mma16816(acc[mi][nj], ah[mi], bb[nj]);  // hi*lo
    };

    const int quad = lane & 3, qrow = lane >> 2;

    // ---- prologue: first tile's chunks 0,1 ----
    const int t0 = blockIdx.x;
    load_chunk(t0, 0, 0);     CP_COMMIT();
    load_chunk(t0, 1, STAGE); CP_COMMIT();

    uint32_t s0 = 0, s1 = STAGE, s2 = 2 * STAGE;

    for (int t = t0; t < NTILES; t += GRID_MAIN) {
        const int tn = t + GRID_MAIN;
        #pragma unroll 1
        for (int kc = 0; kc < N_KCHUNK; kc++) {
            CP_WAIT1();
            __syncthreads();
            if (kc + 2 < N_KCHUNK)      load_chunk(t, kc + 2, s2);
            else if (tn < NTILES)       load_chunk(tn, kc - 14, s2);  // next tile 0,1
            CP_COMMIT();
            compute(0, s0);
            compute(1, s0);
            uint32_t tmp = s0; s0 = s1; s1 = s2; s2 = tmp;
        }

        // ---- epilogue (register-only + read-only centS; no sync needed) ----
        const int mt = t >> 3, bx = t & 7;
        const int b = mt >> 7, ptile = (mt & 127) << 7;
        #pragma unroll
        for (int mi = 0; mi < 2; mi++)
            #pragma unroll
            for (int rv = 0; rv < 2; rv++)
                #pragma unroll
                for (int cb = 0; cb < 4; cb++) {
                    float s = 0.f;
                    #pragma unroll
                    for (int tt = 0; tt < 2; tt++) {
                        int nj = cb * 2 + tt;
                        int n0 = bx * 128 + wc * 64 + nj * 8 + quad * 2;
                        float c0 = centS[n0], c1 = centS[n0 + 1];
                        float d0 = acc[mi][nj][rv * 2 + 0] - c0;
                        float d1 = acc[mi][nj][rv * 2 + 1] - c1;
                        s = fmaf(d0, d0, s);
                        s = fmaf(d1, d1, s);
                        acc[mi][nj][rv * 2 + 0] = 0.f;   // reset for next tile
                        acc[mi][nj][rv * 2 + 1] = 0.f;
                    }
                    s += __shfl_xor_sync(0xffffffffu, s, 1);
                    s += __shfl_xor_sync(0xffffffffu, s, 2);
                    if (quad == cb) {
                        int row = wr * 32 + mi * 16 + rv * 8 + qrow;
                        int cg  = bx * 8 + wc * 4 + cb;
                        out[(((size_t)(b * 64 + cg)) << 14) + ptile + row] = expf(-3.125f * s);
                    }
                }
    }
}

extern "C" void kernel_launch(void* const* d_in, const int* in_sizes, int n_in,
                              void* d_out, int out_size) {
    const float *feat = nullptr, *w = nullptr, *m = nullptr, *Nb = nullptr;
    for (int i = 0; i < n_in; i++) {
        if (in_sizes[i] == 67108864)    feat = (const float*)d_in[i];
        else if (in_sizes[i] == 524288) w    = (const float*)d_in[i];
        else if (in_sizes[i] == 1024)   m    = (const float*)d_in[i];
        else if (in_sizes[i] == 64)     Nb   = (const float*)d_in[i];
    }
    float* out = (float*)d_out;

    static bool attr_set = false;
    if (!attr_set) {
        cudaFuncSetAttribute((const void*)duq_main,
                             cudaFuncAttributeMaxDynamicSharedMemorySize, SMEM_BYTES);
        attr_set = true;
    }

    prep_all<<<16640, 256>>>(feat, w);
    duq_main<<<GRID_MAIN, 256, SMEM_BYTES>>>(m, Nb, out);
}

// round 8
// speedup vs baseline: 1.0708x; 1.0708x over previous
#include <cuda_runtime.h>
#include <cuda_bf16.h>
#include <cstdint>

// ---------------- problem constants ----------------
#define HW       16384           // 128*128 pixels per image
#define N_KCHUNK 16              // K = 512 in chunks of 32
#define NTILES   8192            // 1024 m-tiles x 8 n-tiles
#define GRID_MAIN 296            // 148 SMs x 2 CTAs

// ---------------- smem layout ----------------
// stage = A_hi(8K) A_lo(8K) B_hi(8K) B_lo(8K) = 32KB, 3 stages + cent(4KB)
#define STAGE     32768
#define B_REGION  16384
#define CENT_OFF  (3 * STAGE)
#define SMEM_BYTES (CENT_OFF + 4096)

// scratch: features pre-split to bf16 hi/lo in ldmatrix-canonical tiles.
// chunk (mt, kc) = 16KB: hi[8K] lo[8K]; 1024 mt * 16 kc = 256MB
__device__ uint4 g_feat[16777216];
// weights likewise: chunk (bx, kc) = 16KB; 8 * 16 = 2MB
__device__ uint4 g_w[131072];

// ---------------- helpers ----------------
__device__ __forceinline__ uint32_t smem_u32(const void* p) {
    uint32_t a;
    asm("{ .reg .u64 t; cvta.to.shared.u64 t, %1; cvt.u32.u64 %0, t; }" : "=r"(a) : "l"(p));
    return a;
}
#define CP_ASYNC16(dst, src) \
    asm volatile("cp.async.cg.shared.global [%0], [%1], 16;" :: "r"(dst), "l"(src) : "memory")
#define CP_COMMIT()  asm volatile("cp.async.commit_group;" ::: "memory")
#define CP_WAIT1()   asm volatile("cp.async.wait_group 1;" ::: "memory")

__device__ __forceinline__ void ldsm4(uint32_t* r, uint32_t addr) {
    asm volatile("ldmatrix.sync.aligned.m8n8.x4.shared.b16 {%0,%1,%2,%3}, [%4];"
        : "=r"(r[0]), "=r"(r[1]), "=r"(r[2]), "=r"(r[3]) : "r"(addr));
}
__device__ __forceinline__ void mma16816(float* d, const uint32_t* a, const uint32_t* b) {
    asm volatile("mma.sync.aligned.m16n8k16.row.col.f32.bf16.bf16.f32 "
        "{%0,%1,%2,%3}, {%4,%5,%6,%7}, {%8,%9}, {%0,%1,%2,%3};"
        : "+f"(d[0]), "+f"(d[1]), "+f"(d[2]), "+f"(d[3])
        : "r"(a[0]), "r"(a[1]), "r"(a[2]), "r"(a[3]), "r"(b[0]), "r"(b[1]));
}
__device__ __forceinline__ void split2(float x0, float x1, uint32_t& hi, uint32_t& lo) {
    __nv_bfloat16 h0 = __float2bfloat16(x0);
    __nv_bfloat16 h1 = __float2bfloat16(x1);
    __nv_bfloat16 l0 = __float2bfloat16(x0 - __bfloat162float(h0));
    __nv_bfloat16 l1 = __float2bfloat16(x1 - __bfloat162float(h1));
    hi = (uint32_t)__bfloat16_as_ushort(h0) | ((uint32_t)__bfloat16_as_ushort(h1) << 16);
    lo = (uint32_t)__bfloat16_as_ushort(l0) | ((uint32_t)__bfloat16_as_ushort(l1) << 16);
}

// ---------------- prep: features (+weights) -> hi/lo bf16 canonical tiles ----
// blocks 0..16383: features; blocks 16384..16639: weights (n = c*16+e order)
__global__ void prep_all(const float* __restrict__ feat, const float* __restrict__ w) {
    int tid = threadIdx.x;
    if (blockIdx.x >= 16384) {
        int idx = (blockIdx.x - 16384) * 256 + tid;   // n(1024) x k8(64)
        int n = idx >> 6, k8 = idx & 63;
        int e = n & 15, c = n >> 4;
        const float* src = w + (((size_t)(e * 64 + c)) << 9) + k8 * 8;
        uint32_t hiw[4], low[4];
        #pragma unroll
        for (int i = 0; i < 4; i++) split2(src[2 * i], src[2 * i + 1], hiw[i], low[i]);
        int bx = n >> 7, nl = n & 127, kc = k8 >> 2, k8l = k8 & 3;
        char* dst = (char*)g_w + ((size_t)(bx * 16 + kc)) * 16384;
        uint32_t off = (uint32_t)(((nl >> 3) * 4 + k8l) * 128 + (nl & 7) * 16);
        *(uint4*)(dst + off)        = make_uint4(hiw[0], hiw[1], hiw[2], hiw[3]);
        *(uint4*)(dst + 8192 + off) = make_uint4(low[0], low[1], low[2], low[3]);
        return;
    }
    __shared__ float s[32][128];
    int blk = blockIdx.x;                 // mt*16 + kc
    int mt = blk >> 4, kc = blk & 15;
    int b = mt >> 7, ptile = (mt & 127) << 7;
    const float* src = feat + (((size_t)b << 9) + kc * 32) * HW + ptile;
    int px = tid & 127, kh = tid >> 7;    // kh 0..1
    #pragma unroll
    for (int r = 0; r < 16; r++) {
        int k = r * 2 + kh;
        s[k][px] = src[(size_t)k * HW + px];
    }
    __syncthreads();
    char* dst = (char*)g_feat + (size_t)blk * 16384;
    #pragma unroll
    for (int j = 0; j < 2; j++) {
        int k8 = kh * 2 + j;
        uint32_t hiw[4], low[4];
        #pragma unroll
        for (int i = 0; i < 4; i++)
            split2(s[k8 * 8 + 2 * i][px], s[k8 * 8 + 2 * i + 1][px], hiw[i], low[i]);
        uint32_t off = (uint32_t)(((px >> 3) * 4 + k8) * 128 + (px & 7) * 16);
        *(uint4*)(dst + off)        = make_uint4(hiw[0], hiw[1], hiw[2], hiw[3]);
        *(uint4*)(dst + 8192 + off) = make_uint4(low[0], low[1], low[2], low[3]);
    }
}

// ---------------- main fused kernel: persistent, continuous pipeline ----------
__global__ void __launch_bounds__(256, 2)
duq_main(const float* __restrict__ d_m, const float* __restrict__ d_N,
         float* __restrict__ out) {
    extern __shared__ char smem[];
    const uint32_t sb = smem_u32(smem);

    const int tid  = threadIdx.x;
    const int lane = tid & 31;
    const int wid  = tid >> 5;
    const int wr   = wid >> 1;        // warp m-row 0..3  (m offset wr*32)
    const int wc   = wid & 1;         // warp n-col 0..1  (n offset wc*64)

    // all 1024 centroids once: cent[i], i = c*16 + e
    float* centS = (float*)(smem + CENT_OFF);
    if (tid < 256) {
        #pragma unroll
        for (int r = 0; r < 4; r++) {
            int i = r * 256 + tid;
            centS[i] = d_m[(i & 15) * 64 + (i >> 4)] / d_N[i >> 4];
        }
    }

    // chunk loader: tile t = mt*8 + bx; pure cp.async, 8 x 16B per thread
    const uint32_t dstT = sb + tid * 16;
    auto load_chunk = [&](int t, int kc, uint32_t stByte) {
        int mt = t >> 3, bx = t & 7;
        const char* sa = (const char*)(g_feat + (((size_t)(mt * 16 + kc)) << 10)) + tid * 16;
        const char* sp = (const char*)(g_w    + (((size_t)(bx * 16 + kc)) << 10)) + tid * 16;
        #pragma unroll
        for (int it = 0; it < 4; it++)
            CP_ASYNC16(dstT + stByte + it * 4096, sa + it * 4096);
        #pragma unroll
        for (int it = 0; it < 4; it++)
            CP_ASYNC16(dstT + stByte + B_REGION + it * 4096, sp + it * 4096);
    };

    // ldmatrix lane bases (canonical tiled layout, conflict-free)
    const int g = lane >> 3, r8 = lane & 7;
    const uint32_t baseA = sb + (uint32_t)((((wr * 4 + (g & 1)) * 4 + (g >> 1)) * 128) + r8 * 16);
    const uint32_t baseB = sb + (uint32_t)(B_REGION + (((wc * 8 + (g >> 1)) * 4 + (g & 1)) * 128) + r8 * 16);

    float acc[2][8][4];
    #pragma unroll
    for (int i = 0; i < 2; i++)
        #pragma unroll
        for (int j = 0; j < 8; j++)
            #pragma unroll
            for (int k = 0; k < 4; k++) acc[i][j][k] = 0.f;

    // one 16-K step: 12 ldsm.x4, 48 mma, B-frag registers reused hi->lo
    auto compute = [&](int ks, uint32_t st) {
        uint32_t ah[2][4], al[2][4], bb[8][2];
        const uint32_t aoff = baseA + st + ks * 256;
        const uint32_t boff = baseB + st + ks * 256;
        ldsm4(ah[0], aoff);
        ldsm4(ah[1], aoff + 1024);
        ldsm4(al[0], aoff + 8192);
        ldsm4(al[1], aoff + 8192 + 1024);
        #pragma unroll
        for (int t = 0; t < 4; t++) ldsm4(&bb[2 * t][0], boff + t * 1024);
        #pragma unroll
        for (int mi = 0; mi < 2; mi++)
            #pragma unroll
            for (int nj = 0; nj < 8; nj++) mma16816(acc[mi][nj], ah[mi], bb[nj]);  // hi*hi
        #pragma unroll
        for (int mi = 0; mi < 2; mi++)
            #pragma unroll
            for (int nj = 0; nj < 8; nj++) mma16816(acc[mi][nj], al[mi], bb[nj]);  // lo*hi
        #pragma unroll
        for (int t = 0; t < 4; t++) ldsm4(&bb[2 * t][0], boff + 8192 + t * 1024);  // reuse regs
        #pragma unroll
        for (int mi = 0; mi < 2; mi++)
            #pragma unroll
            for (int nj = 0; nj < 8; nj++) mma16816(acc[mi][nj], ah[mi], bb[nj]);  // hi*lo
    };

    const int quad = lane & 3, qrow = lane >> 2;

    // ---- prologue: first tile's chunks 0,1 ----
    const int t0 = blockIdx.x;
    load_chunk(t0, 0, 0);     CP_COMMIT();
    load_chunk(t0, 1, STAGE); CP_COMMIT();

    uint32_t s0 = 0, s1 = STAGE, s2 = 2 * STAGE;

    #pragma unroll 1
    for (int t = t0; t < NTILES; t += GRID_MAIN) {
        const int tn = t + GRID_MAIN;
        #pragma unroll                              // FULL unroll: static scheduling
        for (int kc = 0; kc < N_KCHUNK; kc++) {
            CP_WAIT1();
            __syncthreads();
            if (kc + 2 < N_KCHUNK)      load_chunk(t, kc + 2, s2);
            else if (tn < NTILES)       load_chunk(tn, kc - 14, s2);  // next tile 0,1
            CP_COMMIT();
            compute(0, s0);
            compute(1, s0);
            uint32_t tmp = s0; s0 = s1; s1 = s2; s2 = tmp;
        }

        // ---- epilogue (register-only + read-only centS; no sync needed) ----
        const int mt = t >> 3, bx = t & 7;
        const int b = mt >> 7, ptile = (mt & 127) << 7;
        #pragma unroll
        for (int mi = 0; mi < 2; mi++)
            #pragma unroll
            for (int rv = 0; rv < 2; rv++)
                #pragma unroll
                for (int cb = 0; cb < 4; cb++) {
                    float s = 0.f;
                    #pragma unroll
                    for (int tt = 0; tt < 2; tt++) {
                        int nj = cb * 2 + tt;
                        int n0 = bx * 128 + wc * 64 + nj * 8 + quad * 2;
                        float c0 = centS[n0], c1 = centS[n0 + 1];
                        float d0 = acc[mi][nj][rv * 2 + 0] - c0;
                        float d1 = acc[mi][nj][rv * 2 + 1] - c1;
                        s = fmaf(d0, d0, s);
                        s = fmaf(d1, d1, s);
                        acc[mi][nj][rv * 2 + 0] = 0.f;   // reset for next tile
                        acc[mi][nj][rv * 2 + 1] = 0.f;
                    }
                    s += __shfl_xor_sync(0xffffffffu, s, 1);
                    s += __shfl_xor_sync(0xffffffffu, s, 2);
                    if (quad == cb) {
                        int row = wr * 32 + mi * 16 + rv * 8 + qrow;
                        int cg  = bx * 8 + wc * 4 + cb;
                        out[(((size_t)(b * 64 + cg)) << 14) + ptile + row] = expf(-3.125f * s);
                    }
                }
    }
}

extern "C" void kernel_launch(void* const* d_in, const int* in_sizes, int n_in,
                              void* d_out, int out_size) {
    const float *feat = nullptr, *w = nullptr, *m = nullptr, *Nb = nullptr;
    for (int i = 0; i < n_in; i++) {
        if (in_sizes[i] == 67108864)    feat = (const float*)d_in[i];
        else if (in_sizes[i] == 524288) w    = (const float*)d_in[i];
        else if (in_sizes[i] == 1024)   m    = (const float*)d_in[i];
        else if (in_sizes[i] == 64)     Nb   = (const float*)d_in[i];
    }
    float* out = (float*)d_out;

    static bool attr_set = false;
    if (!attr_set) {
        cudaFuncSetAttribute((const void*)duq_main,
                             cudaFuncAttributeMaxDynamicSharedMemorySize, SMEM_BYTES);
        attr_set = true;
    }

    prep_all<<<16640, 256>>>(feat, w);
    duq_main<<<GRID_MAIN, 256, SMEM_BYTES>>>(m, Nb, out);
}

// round 9
// speedup vs baseline: 1.1572x; 1.0806x over previous
#include <cuda_runtime.h>
#include <cuda_bf16.h>
#include <cstdint>

// ---------------- problem constants ----------------
#define HW       16384           // 128*128 pixels per image
#define N_KCHUNK 16              // K = 512 in chunks of 32

// ---------------- smem layout ----------------
// stage = A_hi(8K) A_lo(8K) B_hi(8K) B_lo(8K) = 32KB, 3 stages + cent(512B)
#define STAGE     32768
#define B_REGION  16384
#define CENT_OFF  (3 * STAGE)
#define SMEM_BYTES (CENT_OFF + 512)

// scratch: features pre-split to bf16 hi/lo in ldmatrix-canonical tiles.
// chunk (mt, kc) = 16KB: hi[8K] lo[8K]; 1024 mt * 16 kc = 256MB
__device__ uint4 g_feat[16777216];
// weights likewise: chunk (bx, kc) = 16KB; 8 * 16 = 2MB
__device__ uint4 g_w[131072];

// ---------------- helpers ----------------
__device__ __forceinline__ uint32_t smem_u32(const void* p) {
    uint32_t a;
    asm("{ .reg .u64 t; cvta.to.shared.u64 t, %1; cvt.u32.u64 %0, t; }" : "=r"(a) : "l"(p));
    return a;
}
#define CP_ASYNC16(dst, src) \
    asm volatile("cp.async.cg.shared.global [%0], [%1], 16;" :: "r"(dst), "l"(src) : "memory")
#define CP_COMMIT()  asm volatile("cp.async.commit_group;" ::: "memory")
#define CP_WAIT1()   asm volatile("cp.async.wait_group 1;" ::: "memory")

__device__ __forceinline__ void ldsm4(uint32_t* r, uint32_t addr) {
    asm volatile("ldmatrix.sync.aligned.m8n8.x4.shared.b16 {%0,%1,%2,%3}, [%4];"
        : "=r"(r[0]), "=r"(r[1]), "=r"(r[2]), "=r"(r[3]) : "r"(addr));
}
__device__ __forceinline__ void mma16816(float* d, const uint32_t* a, const uint32_t* b) {
    asm volatile("mma.sync.aligned.m16n8k16.row.col.f32.bf16.bf16.f32 "
        "{%0,%1,%2,%3}, {%4,%5,%6,%7}, {%8,%9}, {%0,%1,%2,%3};"
        : "+f"(d[0]), "+f"(d[1]), "+f"(d[2]), "+f"(d[3])
        : "r"(a[0]), "r"(a[1]), "r"(a[2]), "r"(a[3]), "r"(b[0]), "r"(b[1]));
}
__device__ __forceinline__ void split2(float x0, float x1, uint32_t& hi, uint32_t& lo) {
    __nv_bfloat16 h0 = __float2bfloat16(x0);
    __nv_bfloat16 h1 = __float2bfloat16(x1);
    __nv_bfloat16 l0 = __float2bfloat16(x0 - __bfloat162float(h0));
    __nv_bfloat16 l1 = __float2bfloat16(x1 - __bfloat162float(h1));
    hi = (uint32_t)__bfloat16_as_ushort(h0) | ((uint32_t)__bfloat16_as_ushort(h1) << 16);
    lo = (uint32_t)__bfloat16_as_ushort(l0) | ((uint32_t)__bfloat16_as_ushort(l1) << 16);
}

// ---------------- prep: features (+weights) -> hi/lo bf16 canonical tiles ----
// blocks 0..16383: features; blocks 16384..16639: weights (n = c*16+e order)
__global__ void prep_all(const float* __restrict__ feat, const float* __restrict__ w) {
    int tid = threadIdx.x;
    if (blockIdx.x >= 16384) {
        int idx = (blockIdx.x - 16384) * 256 + tid;   // n(1024) x k8(64)
        int n = idx >> 6, k8 = idx & 63;
        int e = n & 15, c = n >> 4;
        const float* src = w + (((size_t)(e * 64 + c)) << 9) + k8 * 8;
        uint32_t hiw[4], low[4];
        #pragma unroll
        for (int i = 0; i < 4; i++) split2(src[2 * i], src[2 * i + 1], hiw[i], low[i]);
        int bx = n >> 7, nl = n & 127, kc = k8 >> 2, k8l = k8 & 3;
        char* dst = (char*)g_w + ((size_t)(bx * 16 + kc)) * 16384;
        uint32_t off = (uint32_t)(((nl >> 3) * 4 + k8l) * 128 + (nl & 7) * 16);
        *(uint4*)(dst + off)        = make_uint4(hiw[0], hiw[1], hiw[2], hiw[3]);
        *(uint4*)(dst + 8192 + off) = make_uint4(low[0], low[1], low[2], low[3]);
        return;
    }
    __shared__ float s[32][128];
    int blk = blockIdx.x;                 // mt*16 + kc
    int mt = blk >> 4, kc = blk & 15;
    int b = mt >> 7, ptile = (mt & 127) << 7;
    const float* src = feat + (((size_t)b << 9) + kc * 32) * HW + ptile;
    int px = tid & 127, kh = tid >> 7;    // kh 0..1
    #pragma unroll
    for (int r = 0; r < 16; r++) {
        int k = r * 2 + kh;
        s[k][px] = src[(size_t)k * HW + px];
    }
    __syncthreads();
    char* dst = (char*)g_feat + (size_t)blk * 16384;
    #pragma unroll
    for (int j = 0; j < 2; j++) {
        int k8 = kh * 2 + j;
        uint32_t hiw[4], low[4];
        #pragma unroll
        for (int i = 0; i < 4; i++)
            split2(s[k8 * 8 + 2 * i][px], s[k8 * 8 + 2 * i + 1][px], hiw[i], low[i]);
        uint32_t off = (uint32_t)(((px >> 3) * 4 + k8) * 128 + (px & 7) * 16);
        *(uint4*)(dst + off)        = make_uint4(hiw[0], hiw[1], hiw[2], hiw[3]);
        *(uint4*)(dst + 8192 + off) = make_uint4(low[0], low[1], low[2], low[3]);
    }
}

// ---------------- main fused kernel (one tile per CTA) ----------------------
__global__ void __launch_bounds__(256, 2)
duq_main(const float* __restrict__ d_m, const float* __restrict__ d_N,
         float* __restrict__ out) {
    extern __shared__ char smem[];
    const uint32_t sb = smem_u32(smem);

    const int tid  = threadIdx.x;
    const int lane = tid & 31;
    const int wid  = tid >> 5;
    const int wr   = wid >> 1;        // warp m-row 0..3  (m offset wr*32)
    const int wc   = wid & 1;         // warp n-col 0..1  (n offset wc*64)
    const int bx   = blockIdx.x;      // n-tile 0..7
    const int mt   = blockIdx.y;      // m-tile 0..1023
    const int b    = mt >> 7;
    const int ptile = (mt & 127) << 7;

    // centroids for this n-tile only: cent[i], n_glob = bx*128 + i = c*16 + e
    float* centS = (float*)(smem + CENT_OFF);
    if (tid < 128) {
        int ng = bx * 128 + tid;
        centS[tid] = d_m[(ng & 15) * 64 + (ng >> 4)] / d_N[ng >> 4];
    }

    // per-thread source pointers for the chunk loader (advance by 16KB/chunk)
    const char* srcA = (const char*)(g_feat + ((size_t)(mt * 16) << 10)) + tid * 16;
    const char* srcB = (const char*)(g_w    + ((size_t)(bx * 16) << 10)) + tid * 16;
    const uint32_t dstT = sb + tid * 16;
    auto load_chunk = [&](int kc, uint32_t stByte) {
        const char* sa = srcA + ((size_t)kc << 14);
        const char* sp = srcB + ((size_t)kc << 14);
        #pragma unroll
        for (int it = 0; it < 4; it++)
            CP_ASYNC16(dstT + stByte + it * 4096, sa + it * 4096);
        #pragma unroll
        for (int it = 0; it < 4; it++)
            CP_ASYNC16(dstT + stByte + B_REGION + it * 4096, sp + it * 4096);
    };

    // ldmatrix lane bases (canonical tiled layout, conflict-free)
    const int g = lane >> 3, r8 = lane & 7;
    const uint32_t baseA = sb + (uint32_t)((((wr * 4 + (g & 1)) * 4 + (g >> 1)) * 128) + r8 * 16);
    const uint32_t baseB = sb + (uint32_t)(B_REGION + (((wc * 8 + (g >> 1)) * 4 + (g & 1)) * 128) + r8 * 16);

    float acc[2][8][4];
    #pragma unroll
    for (int i = 0; i < 2; i++)
        #pragma unroll
        for (int j = 0; j < 8; j++)
            #pragma unroll
            for (int k = 0; k < 4; k++) acc[i][j][k] = 0.f;

    uint32_t ah[2][4], al[2][4], bb[8][2];

    // fragment batch: A hi/lo + B hi (8 ldsm.x4)
    auto ldsm_batch = [&](uint32_t aoff, uint32_t boff) {
        ldsm4(ah[0], aoff);
        ldsm4(ah[1], aoff + 1024);
        ldsm4(al[0], aoff + 8192);
        ldsm4(al[1], aoff + 8192 + 1024);
        #pragma unroll
        for (int t = 0; t < 4; t++) ldsm4(&bb[2 * t][0], boff + t * 1024);
    };
    // 48 mma; B-lo ldsm interleaved into the lo*hi pass (reloads dead bb pairs)
    auto mma_passes = [&](uint32_t boff) {
        #pragma unroll
        for (int mi = 0; mi < 2; mi++)
            #pragma unroll
            for (int nj = 0; nj < 8; nj++) mma16816(acc[mi][nj], ah[mi], bb[nj]);  // hi*hi
        #pragma unroll
        for (int t = 0; t < 4; t++) {                                              // lo*hi
            mma16816(acc[0][2 * t],     al[0], bb[2 * t]);
            mma16816(acc[1][2 * t],     al[1], bb[2 * t]);
            mma16816(acc[0][2 * t + 1], al[0], bb[2 * t + 1]);
            mma16816(acc[1][2 * t + 1], al[1], bb[2 * t + 1]);
            ldsm4(&bb[2 * t][0], boff + 8192 + t * 1024);   // reload pair t -> B_lo
        }
        #pragma unroll
        for (int mi = 0; mi < 2; mi++)
            #pragma unroll
            for (int nj = 0; nj < 8; nj++) mma16816(acc[mi][nj], ah[mi], bb[nj]);  // hi*lo
    };

    // ---- prologue: chunks 0,1 into stages 0,1 ----
    load_chunk(0, 0);     CP_COMMIT();
    load_chunk(1, STAGE); CP_COMMIT();

    uint32_t s0 = 0, s1 = STAGE, s2 = 2 * STAGE;  // s0=compute, s2=load dest
    #pragma unroll
    for (int kc = 0; kc < N_KCHUNK; kc++) {
        CP_WAIT1();
        __syncthreads();
        // ks=0 fragment loads FIRST (mma can start while cp.async issues)
        ldsm_batch(baseA + s0, baseB + s0);
        if (kc + 2 < N_KCHUNK) load_chunk(kc + 2, s2);
        CP_COMMIT();          // one group per iteration (possibly empty)
        mma_passes(baseB + s0);
        // ks=1
        ldsm_batch(baseA + s0 + 256, baseB + s0 + 256);
        mma_passes(baseB + s0 + 256);
        uint32_t tmp = s0; s0 = s1; s1 = s2; s2 = tmp;
    }

    // ---- epilogue: S = sum_e (emb - cent)^2 over 16 contiguous n, exp ----
    const int quad = lane & 3, qrow = lane >> 2;
    #pragma unroll
    for (int mi = 0; mi < 2; mi++)
        #pragma unroll
        for (int rv = 0; rv < 2; rv++)
            #pragma unroll
            for (int cb = 0; cb < 4; cb++) {
                float s = 0.f;
                #pragma unroll
                for (int tt = 0; tt < 2; tt++) {
                    int nj = cb * 2 + tt;
                    int n0 = wc * 64 + nj * 8 + quad * 2;
                    float c0 = centS[n0], c1 = centS[n0 + 1];
                    float d0 = acc[mi][nj][rv * 2 + 0] - c0;
                    float d1 = acc[mi][nj][rv * 2 + 1] - c1;
                    s = fmaf(d0, d0, s);
                    s = fmaf(d1, d1, s);
                }
                s += __shfl_xor_sync(0xffffffffu, s, 1);
                s += __shfl_xor_sync(0xffffffffu, s, 2);
                if (quad == cb) {
                    int row = wr * 32 + mi * 16 + rv * 8 + qrow;
                    int cg  = bx * 8 + wc * 4 + cb;
                    out[(((size_t)(b * 64 + cg)) << 14) + ptile + row] = expf(-3.125f * s);
                }
            }
}

extern "C" void kernel_launch(void* const* d_in, const int* in_sizes, int n_in,
                              void* d_out, int out_size) {
    const float *feat = nullptr, *w = nullptr, *m = nullptr, *Nb = nullptr;
    for (int i = 0; i < n_in; i++) {
        if (in_sizes[i] == 67108864)    feat = (const float*)d_in[i];
        else if (in_sizes[i] == 524288) w    = (const float*)d_in[i];
        else if (in_sizes[i] == 1024)   m    = (const float*)d_in[i];
        else if (in_sizes[i] == 64)     Nb   = (const float*)d_in[i];
    }
    float* out = (float*)d_out;

    static bool attr_set = false;
    if (!attr_set) {
        cudaFuncSetAttribute((const void*)duq_main,
                             cudaFuncAttributeMaxDynamicSharedMemorySize, SMEM_BYTES);
        attr_set = true;
    }

    prep_all<<<16640, 256>>>(feat, w);
    duq_main<<<dim3(8, 1024, 1), 256, SMEM_BYTES>>>(m, Nb, out);
}